// round 11
// baseline (speedup 1.0000x reference)
#include <cuda_runtime.h>
#include <cuda_bf16.h>
#include <cstdint>

// Problem constants
#define TT 64
#define NROWS 2048
#define DD 512
#define KDIM (2*DD)            // 1024
#define ND (NROWS * DD)        // 1,048,576

// ---------------------------------------------------------------------------
// Device scratch (no allocations allowed)
// ---------------------------------------------------------------------------
__device__ float g_state0[ND];                       // states[0] fp32 (carry only)
__device__ __nv_bfloat16 g_h_hi[2][ND];              // ping-pong bf16 split of h
__device__ __nv_bfloat16 g_h_lo[2][ND];
__device__ __nv_bfloat16 g_wt_hi[DD * KDIM];         // W^T split: [512 n][1024 k]
__device__ __nv_bfloat16 g_wt_lo[DD * KDIM];
__device__ __nv_bfloat16 g_s_hi[TT * ND];            // pre-split static (hi)
__device__ __nv_bfloat16 g_s_lo[TT * ND];            // pre-split static (lo)

// ---------------------------------------------------------------------------
// Warp-level primitives (sm_80+ PTX, safe for compute_103)
// ---------------------------------------------------------------------------
__device__ __forceinline__ uint32_t smem_u32(const void* p) {
    uint32_t a;
    asm("{ .reg .u64 t; cvta.to.shared.u64 t, %1; cvt.u32.u64 %0, t; }"
        : "=r"(a) : "l"(p));
    return a;
}

__device__ __forceinline__ void ldsm_x4(uint32_t* r, uint32_t addr) {
    asm volatile("ldmatrix.sync.aligned.m8n8.x4.shared.b16 {%0,%1,%2,%3}, [%4];"
                 : "=r"(r[0]), "=r"(r[1]), "=r"(r[2]), "=r"(r[3]) : "r"(addr));
}

__device__ __forceinline__ void mma_bf16(float* d, const uint32_t* a,
                                         const uint32_t* b) {
    asm volatile(
        "mma.sync.aligned.m16n8k16.row.col.f32.bf16.bf16.f32 "
        "{%0,%1,%2,%3}, {%4,%5,%6,%7}, {%8,%9}, {%0,%1,%2,%3};"
        : "+f"(d[0]), "+f"(d[1]), "+f"(d[2]), "+f"(d[3])
        : "r"(a[0]), "r"(a[1]), "r"(a[2]), "r"(a[3]), "r"(b[0]), "r"(b[1]));
}

__device__ __forceinline__ void cp16(uint32_t dst, const void* src) {
    asm volatile("cp.async.cg.shared.global [%0], [%1], 16;"
                 :: "r"(dst), "l"(src));
}
__device__ __forceinline__ void cp_commit() {
    asm volatile("cp.async.commit_group;");
}
template <int N>
__device__ __forceinline__ void cp_wait() {
    asm volatile("cp.async.wait_group %0;" :: "n"(N));
}

// ---------------------------------------------------------------------------
// Step kernel:
//   MM = h_prev @ W[0:512] + static_t @ W[512:1024]   (split-bf16, fp32 acc)
//   h  = sigmoid(MM*thr + h_prev*(1-thr)) * exp(-1/2)
// CTA tile 128x32, 8 warps stacked in M (warp tile 16x32), BK=32.
// 4-stage cp.async pipeline; grid 256 CTAs, 2 CTAs/SM co-resident.
// ---------------------------------------------------------------------------
#define BM 128
#define BN 32
#define BK 32
#define NCHUNK (KDIM / BK)     // 32
#define STAGES 4

// per-stage byte offsets (every tile row = 32 bf16 + 8 pad = 80B)
#define ST_AHI 0
#define ST_ALO 10240           // 128*80
#define ST_BHI 20480
#define ST_BLO 23040           // + 32*80
#define STAGE_BYTES 25600
#define SMEM_TOTAL (STAGES * STAGE_BYTES)   // 102400 per CTA (2/SM = 200KB)

__global__ void __launch_bounds__(256, 2) step_mma_kernel(
    const __nv_bfloat16* __restrict__ h_hi,   // [N, DD] phase-0 A (hi)
    const __nv_bfloat16* __restrict__ h_lo,
    const __nv_bfloat16* __restrict__ s_hi,   // [N, DD] phase-1 A (hi), this step
    const __nv_bfloat16* __restrict__ s_lo,
    const float* __restrict__ h_prev,         // [N, DD] fp32 (gate input)
    const float* __restrict__ thr,            // [N]
    const __nv_bfloat16* __restrict__ wt_hi,  // [DD, KDIM] W^T hi
    const __nv_bfloat16* __restrict__ wt_lo,
    float* __restrict__ h_out,                // [N, DD] fp32
    __nv_bfloat16* __restrict__ o_hi,         // split of new h
    __nv_bfloat16* __restrict__ o_lo)
{
    extern __shared__ char smem[];
    const uint32_t sb = smem_u32(smem);

    const int tid  = threadIdx.x;
    const int lane = tid & 31;
    const int warp = tid >> 5;           // 0..7, stacked in M
    const int m_base = warp * 16;
    const int row0 = blockIdx.y * BM;
    const int col0 = blockIdx.x * BN;

    // ldmatrix lane maps
    // A (16x16 tile, x4): lanes 0-15 -> rows, k0; lanes 16-31 -> rows, k0+8
    const int a_lrow = (lane & 7) + ((lane >> 3) & 1) * 8;
    const int a_koff = ((lane >> 4) & 1) * 8;
    // B paired x4 (two 8n x 16k frags): groups of 8 lanes ->
    //   (n0,k0), (n0,k0+8), (n0+8,k0), (n0+8,k0+8)
    const int b_lrow = ((lane >> 4) & 1) * 8 + (lane & 7);
    const int b_koff = ((lane >> 3) & 1) * 8;

    float acc[4][4];                     // ni = 0..3 (32 N), 16x8 each
#pragma unroll
    for (int ni = 0; ni < 4; ++ni)
#pragma unroll
        for (int j = 0; j < 4; ++j) acc[ni][j] = 0.0f;

    // ---- async tile fill for chunk c into stage (c % STAGES) ----
    // A: 128 rows x 32 k (hi+lo): 512 cp16 per tile -> 2/thread each
    // B:  32 rows x 32 k (hi+lo): 128 cp16 per tile -> tid<128, 1 each
    auto issue_chunk = [&](int c) {
        const uint32_t st = sb + (uint32_t)(c & (STAGES - 1)) * STAGE_BYTES;
        const int ph  = c >> 4;
        const int kkA = (c & 15) * BK;
        const int kkW = c * BK;
        const __nv_bfloat16* ah = ph ? s_hi : h_hi;
        const __nv_bfloat16* al = ph ? s_lo : h_lo;
#pragma unroll
        for (int i = 0; i < 2; ++i) {
            const int o = tid + i * 256;       // 0..511
            const int r = o >> 2;              // 0..127
            const int q = o & 3;
            const size_t src = (size_t)(row0 + r) * DD + kkA + q * 8;
            const uint32_t dst = st + (uint32_t)(r * 80 + q * 16);
            cp16(dst + ST_AHI, ah + src);
            cp16(dst + ST_ALO, al + src);
        }
        if (tid < 128) {
            const int r = tid >> 2;            // 0..31
            const int q = tid & 3;
            const size_t src = (size_t)(col0 + r) * KDIM + kkW + q * 8;
            const uint32_t dst = st + (uint32_t)(r * 80 + q * 16);
            cp16(dst + ST_BHI, wt_hi + src);
            cp16(dst + ST_BLO, wt_lo + src);
        }
        cp_commit();
    };

    // prologue: stages 0..2 in flight
    issue_chunk(0);
    issue_chunk(1);
    issue_chunk(2);

#pragma unroll 1
    for (int c = 0; c < NCHUNK; ++c) {
        cp_wait<2>();            // chunk c landed
        __syncthreads();         // all warps done reading stage (c-1)%4

        if (c + 3 < NCHUNK) issue_chunk(c + 3);   // refills stage (c-1)%4
        else cp_commit();        // keep group count consistent

        const uint32_t st = sb + (uint32_t)(c & (STAGES - 1)) * STAGE_BYTES;

#pragma unroll
        for (int ks = 0; ks < 2; ++ks) {
            const int k0 = ks * 16;
            uint32_t af_hi[4], af_lo[4], bq_hi[2][4], bq_lo[2][4];
            {
                const uint32_t ro =
                    (uint32_t)((m_base + a_lrow) * 80 + (k0 + a_koff) * 2);
                ldsm_x4(af_hi, st + ST_AHI + ro);
                ldsm_x4(af_lo, st + ST_ALO + ro);
            }
#pragma unroll
            for (int p = 0; p < 2; ++p) {      // ni pairs (0,1) and (2,3)
                const uint32_t ro =
                    (uint32_t)((p * 16 + b_lrow) * 80 + (k0 + b_koff) * 2);
                ldsm_x4(bq_hi[p], st + ST_BHI + ro);
                ldsm_x4(bq_lo[p], st + ST_BLO + ro);
            }
#pragma unroll
            for (int ni = 0; ni < 4; ++ni) {
                const uint32_t* bh = &bq_hi[ni >> 1][(ni & 1) * 2];
                const uint32_t* bl = &bq_lo[ni >> 1][(ni & 1) * 2];
                mma_bf16(acc[ni], af_hi, bh);  // hi*hi
                mma_bf16(acc[ni], af_hi, bl);  // hi*lo
                mma_bf16(acc[ni], af_lo, bh);  // lo*hi
            }
        }
    }

    // ---- epilogue: gated sigmoid update, write fp32 state + bf16 split ----
    const float DEC = 0.6065306597126334f;  // exp(-0.5)
    const int tr = lane >> 2;
    const int tg = lane & 3;
#pragma unroll
    for (int half = 0; half < 2; ++half) {
        const int r = row0 + m_base + half * 8 + tr;
        const float tv = thr[r];
        const float ov = 1.0f - tv;
        const size_t base = (size_t)r * DD;
#pragma unroll
        for (int ni = 0; ni < 4; ++ni) {
            const int cn = col0 + ni * 8 + 2 * tg;
            const float2 hp = *(const float2*)(h_prev + base + cn);
            const float z0 = acc[ni][half * 2 + 0] * tv + hp.x * ov;
            const float z1 = acc[ni][half * 2 + 1] * tv + hp.y * ov;
            float2 res;
            res.x = DEC / (1.0f + __expf(-z0));
            res.y = DEC / (1.0f + __expf(-z1));
            *(float2*)(h_out + base + cn) = res;

            __nv_bfloat162 hh, ll;
            hh.x = __float2bfloat16(res.x);
            hh.y = __float2bfloat16(res.y);
            ll.x = __float2bfloat16(res.x - __bfloat162float(hh.x));
            ll.y = __float2bfloat16(res.y - __bfloat162float(hh.y));
            *(__nv_bfloat162*)(o_hi + base + cn) = hh;
            *(__nv_bfloat162*)(o_lo + base + cn) = ll;
        }
    }
}

// ---------------------------------------------------------------------------
// Prep: transpose + split W  ->  Wt[n][k] = W[k][n], bf16 hi/lo
// ---------------------------------------------------------------------------
__global__ void prep_w_kernel(const float* __restrict__ W,
                              __nv_bfloat16* __restrict__ wt_hi,
                              __nv_bfloat16* __restrict__ wt_lo)
{
    __shared__ float tile[32][33];
    const int n0 = blockIdx.x * 32;
    const int k0 = blockIdx.y * 32;
    const int tx = threadIdx.x;       // 0..31
    const int ty = threadIdx.y;       // 0..7
#pragma unroll
    for (int i = 0; i < 4; ++i)
        tile[ty + i * 8][tx] = W[(size_t)(k0 + ty + i * 8) * DD + n0 + tx];
    __syncthreads();
#pragma unroll
    for (int i = 0; i < 4; ++i) {
        const int a = ty + i * 8;
        const float v = tile[tx][a];
        const __nv_bfloat16 hb = __float2bfloat16(v);
        const size_t dst = (size_t)(n0 + a) * KDIM + k0 + tx;
        wt_hi[dst] = hb;
        wt_lo[dst] = __float2bfloat16(v - __bfloat162float(hb));
    }
}

// ---------------------------------------------------------------------------
// Split fp32 -> bf16 hi/lo (used for h0 and for ALL static data)
// ---------------------------------------------------------------------------
__global__ void split_kernel(const float* __restrict__ x,
                             __nv_bfloat16* __restrict__ hi,
                             __nv_bfloat16* __restrict__ lo,
                             long long n_elem)
{
    const long long i = ((long long)blockIdx.x * blockDim.x + threadIdx.x) * 4;
    if (i >= n_elem) return;
    const float4 v = *(const float4*)(x + i);
    __nv_bfloat162 h01, h23, l01, l23;
    h01.x = __float2bfloat16(v.x); h01.y = __float2bfloat16(v.y);
    h23.x = __float2bfloat16(v.z); h23.y = __float2bfloat16(v.w);
    l01.x = __float2bfloat16(v.x - __bfloat162float(h01.x));
    l01.y = __float2bfloat16(v.y - __bfloat162float(h01.y));
    l23.x = __float2bfloat16(v.z - __bfloat162float(h23.x));
    l23.y = __float2bfloat16(v.w - __bfloat162float(h23.y));
    *(__nv_bfloat162*)(hi + i)     = h01;
    *(__nv_bfloat162*)(hi + i + 2) = h23;
    *(__nv_bfloat162*)(lo + i)     = l01;
    *(__nv_bfloat162*)(lo + i + 2) = l23;
}

// ---------------------------------------------------------------------------
// out2[t] = states[t+1] - states[t]
// ---------------------------------------------------------------------------
__global__ void diff_kernel(const float* __restrict__ s0,
                            const float* __restrict__ out0,
                            float* __restrict__ out2)
{
    long long idx = ((long long)blockIdx.x * blockDim.x + threadIdx.x) * 4;
    const long long total = 63LL * ND;
    if (idx >= total) return;
    const int t = (int)(idx / ND);
    const long long r = idx - (long long)t * ND;
    const float* sp1 = out0 + (long long)(t + 1) * ND + r;
    const float* sp0 = (t == 0) ? (s0 + r) : (out0 + (long long)t * ND + r);
    float4 a = *(const float4*)sp1;
    float4 b = *(const float4*)sp0;
    float4 d;
    d.x = a.x - b.x; d.y = a.y - b.y; d.z = a.z - b.z; d.w = a.w - b.w;
    *(float4*)(out2 + idx) = d;
}

// ---------------------------------------------------------------------------
// Inputs: static [64,2048,512], thr [64,2048,1], h0 [2048,512], w1 [1024,512]
// Output: out0 [64,2048,512] | out1 [2048,512] | out2 [63,2048,512]
// ---------------------------------------------------------------------------
extern "C" void kernel_launch(void* const* d_in, const int* in_sizes, int n_in,
                              void* d_out, int out_size)
{
    const float* S   = (const float*)d_in[0];
    const float* thr = (const float*)d_in[1];
    const float* h0  = (const float*)d_in[2];
    const float* W   = (const float*)d_in[3];

    float* out0 = (float*)d_out;
    float* out1 = out0 + (long long)TT * ND;
    float* out2 = out1 + ND;

    float* s0 = nullptr;
    __nv_bfloat16 *hhi = nullptr, *hlo = nullptr, *wth = nullptr, *wtl = nullptr;
    __nv_bfloat16 *shi = nullptr, *slo = nullptr;
    cudaGetSymbolAddress((void**)&s0, g_state0);
    cudaGetSymbolAddress((void**)&hhi, g_h_hi);
    cudaGetSymbolAddress((void**)&hlo, g_h_lo);
    cudaGetSymbolAddress((void**)&wth, g_wt_hi);
    cudaGetSymbolAddress((void**)&wtl, g_wt_lo);
    cudaGetSymbolAddress((void**)&shi, g_s_hi);
    cudaGetSymbolAddress((void**)&slo, g_s_lo);
    __nv_bfloat16* hhi_b[2] = {hhi, hhi + ND};
    __nv_bfloat16* hlo_b[2] = {hlo, hlo + ND};

    cudaFuncSetAttribute(step_mma_kernel,
                         cudaFuncAttributeMaxDynamicSharedMemorySize, SMEM_TOTAL);

    // one-time prep (per launch)
    prep_w_kernel<<<dim3(16, 32), dim3(32, 8)>>>(W, wth, wtl);
    split_kernel<<<ND / 4 / 256, 256>>>(h0, hhi_b[0], hlo_b[0], (long long)ND);
    split_kernel<<<(unsigned)((long long)TT * ND / 4 / 256), 256>>>(
        S, shi, slo, (long long)TT * ND);

    const dim3 grid(DD / BN, NROWS / BM);  // (16, 16) = 256 CTAs

    // t = 0: carry-only state -> scratch; reads split buf0, writes buf1
    step_mma_kernel<<<grid, 256, SMEM_TOTAL>>>(
        hhi_b[0], hlo_b[0], shi, slo, h0, thr, wth, wtl,
        s0, hhi_b[1], hlo_b[1]);
    cudaMemcpyAsync(out0, h0, (size_t)ND * sizeof(float), cudaMemcpyDeviceToDevice);

    for (int t = 1; t < TT; ++t) {
        const int in = t & 1;
        const float* hp = (t == 1) ? (const float*)s0
                                   : (out0 + (long long)(t - 1) * ND);
        step_mma_kernel<<<grid, 256, SMEM_TOTAL>>>(
            hhi_b[in], hlo_b[in],
            shi + (long long)t * ND, slo + (long long)t * ND,
            hp, thr + (long long)t * NROWS,
            wth, wtl,
            out0 + (long long)t * ND,
            hhi_b[in ^ 1], hlo_b[in ^ 1]);
    }

    cudaMemcpyAsync(out1, out0 + 63LL * ND, (size_t)ND * sizeof(float),
                    cudaMemcpyDeviceToDevice);

    const long long total4 = (63LL * ND) / 4;
    const int threads = 256;
    const unsigned blocks = (unsigned)((total4 + threads - 1) / threads);
    diff_kernel<<<blocks, threads>>>(s0, out0, out2);
}

// round 13
// speedup vs baseline: 1.2932x; 1.2932x over previous
#include <cuda_runtime.h>
#include <cuda_bf16.h>
#include <cstdint>

// Problem constants
#define TT 64
#define NROWS 2048
#define DD 512
#define KDIM (2*DD)            // 1024
#define ND (NROWS * DD)        // 1,048,576

// ---------------------------------------------------------------------------
// Device scratch (no allocations allowed)
// ---------------------------------------------------------------------------
__device__ float g_state0[ND];                       // states[0] fp32 (carry only)
__device__ __nv_bfloat16 g_h_hi[2][ND];              // ping-pong bf16 split of h
__device__ __nv_bfloat16 g_h_lo[2][ND];
__device__ __nv_bfloat16 g_wt_hi[DD * KDIM];         // W^T split: [512 n][1024 k]
__device__ __nv_bfloat16 g_wt_lo[DD * KDIM];
__device__ __nv_bfloat16 g_s_hi[TT * ND];            // pre-split static (hi)
__device__ __nv_bfloat16 g_s_lo[TT * ND];            // pre-split static (lo)

// ---------------------------------------------------------------------------
// Warp-level primitives (sm_80+ PTX, safe for compute_103)
// ---------------------------------------------------------------------------
__device__ __forceinline__ uint32_t smem_u32(const void* p) {
    uint32_t a;
    asm("{ .reg .u64 t; cvta.to.shared.u64 t, %1; cvt.u32.u64 %0, t; }"
        : "=r"(a) : "l"(p));
    return a;
}

__device__ __forceinline__ void ldsm_x4(uint32_t* r, uint32_t addr) {
    asm volatile("ldmatrix.sync.aligned.m8n8.x4.shared.b16 {%0,%1,%2,%3}, [%4];"
                 : "=r"(r[0]), "=r"(r[1]), "=r"(r[2]), "=r"(r[3]) : "r"(addr));
}

__device__ __forceinline__ void mma_bf16(float* d, const uint32_t* a,
                                         const uint32_t* b) {
    asm volatile(
        "mma.sync.aligned.m16n8k16.row.col.f32.bf16.bf16.f32 "
        "{%0,%1,%2,%3}, {%4,%5,%6,%7}, {%8,%9}, {%0,%1,%2,%3};"
        : "+f"(d[0]), "+f"(d[1]), "+f"(d[2]), "+f"(d[3])
        : "r"(a[0]), "r"(a[1]), "r"(a[2]), "r"(a[3]), "r"(b[0]), "r"(b[1]));
}

__device__ __forceinline__ void cp16(uint32_t dst, const void* src) {
    asm volatile("cp.async.cg.shared.global [%0], [%1], 16;"
                 :: "r"(dst), "l"(src));
}
__device__ __forceinline__ void cp_commit() {
    asm volatile("cp.async.commit_group;");
}
template <int N>
__device__ __forceinline__ void cp_wait() {
    asm volatile("cp.async.wait_group %0;" :: "n"(N));
}

// XOR swizzle for 64B rows (4x16B quads): conflict-free for 8-row ldmatrix
// phases and warp STS. phys_quad = q ^ ((r>>1)&3).
__device__ __forceinline__ uint32_t swz_off(int r, int q) {
    return (uint32_t)((r << 6) + ((q ^ ((r >> 1) & 3)) << 4));
}

// ---------------------------------------------------------------------------
// Step kernel:
//   MM = h_prev @ W[0:512] + static_t @ W[512:1024]   (split-bf16, fp32 acc)
//   h  = sigmoid(MM*thr + h_prev*(1-thr)) * exp(-1/2)
// CTA tile 128x32, 8 warps stacked in M (warp tile 16x32), BK=32.
// 5-stage cp.async pipeline (4-deep prefetch); 2 CTAs/SM.
// ---------------------------------------------------------------------------
#define BM 128
#define BN 32
#define BK 32
#define NCHUNK (KDIM / BK)     // 32
#define STAGES 5

// per-stage byte offsets; rows are exactly 64B (32 bf16), XOR-swizzled
#define ST_AHI 0
#define ST_ALO 8192            // 128*64
#define ST_BHI 16384
#define ST_BLO 18432           // + 32*64
#define STAGE_BYTES 20480
#define SMEM_TOTAL (STAGES * STAGE_BYTES)   // 102400 per CTA (2/SM = 200KB)

__global__ void __launch_bounds__(256, 2) step_mma_kernel(
    const __nv_bfloat16* __restrict__ h_hi,   // [N, DD] phase-0 A (hi)
    const __nv_bfloat16* __restrict__ h_lo,
    const __nv_bfloat16* __restrict__ s_hi,   // [N, DD] phase-1 A (hi), this step
    const __nv_bfloat16* __restrict__ s_lo,
    const float* __restrict__ h_prev,         // [N, DD] fp32 (gate input)
    const float* __restrict__ thr,            // [N]
    const __nv_bfloat16* __restrict__ wt_hi,  // [DD, KDIM] W^T hi
    const __nv_bfloat16* __restrict__ wt_lo,
    float* __restrict__ h_out,                // [N, DD] fp32
    __nv_bfloat16* __restrict__ o_hi,         // split of new h
    __nv_bfloat16* __restrict__ o_lo)
{
    extern __shared__ char smem[];
    const uint32_t sb = smem_u32(smem);

    const int tid  = threadIdx.x;
    const int lane = tid & 31;
    const int warp = tid >> 5;           // 0..7, stacked in M
    const int m_base = warp * 16;
    const int row0 = blockIdx.y * BM;
    const int col0 = blockIdx.x * BN;

    // ldmatrix lane maps
    // A (16x16, x4): lanes 0-15 -> rows m..m+15 @ k0; lanes 16-31 -> @ k0+8
    const int a_lrow = (lane & 7) + ((lane >> 3) & 1) * 8;
    const int a_koff = ((lane >> 4) & 1) * 8;
    // B paired x4: 8-lane groups -> (n0,k0),(n0,k0+8),(n0+8,k0),(n0+8,k0+8)
    const int b_lrow = ((lane >> 4) & 1) * 8 + (lane & 7);
    const int b_koff = ((lane >> 3) & 1) * 8;

    float acc_hh[4][4];                  // hi*hi accumulators
    float acc_x[4][4];                   // hi*lo + lo*hi accumulators
#pragma unroll
    for (int ni = 0; ni < 4; ++ni)
#pragma unroll
        for (int j = 0; j < 4; ++j) { acc_hh[ni][j] = 0.0f; acc_x[ni][j] = 0.0f; }

    // ---- async tile fill for chunk c into stage (c % STAGES) ----
    auto issue_chunk = [&](int c) {
        const uint32_t st = sb + (uint32_t)(c % STAGES) * STAGE_BYTES;
        const int ph  = c >> 4;
        const int kkA = (c & 15) * BK;
        const int kkW = c * BK;
        const __nv_bfloat16* ah = ph ? s_hi : h_hi;
        const __nv_bfloat16* al = ph ? s_lo : h_lo;
#pragma unroll
        for (int i = 0; i < 2; ++i) {
            const int o = tid + i * 256;       // 0..511
            const int r = o >> 2;              // 0..127
            const int q = o & 3;
            const size_t src = (size_t)(row0 + r) * DD + kkA + q * 8;
            const uint32_t dst = st + swz_off(r, q);
            cp16(dst + ST_AHI, ah + src);
            cp16(dst + ST_ALO, al + src);
        }
        if (tid < 128) {
            const int r = tid >> 2;            // 0..31
            const int q = tid & 3;
            const size_t src = (size_t)(col0 + r) * KDIM + kkW + q * 8;
            const uint32_t dst = st + swz_off(r, q);
            cp16(dst + ST_BHI, wt_hi + src);
            cp16(dst + ST_BLO, wt_lo + src);
        }
        cp_commit();
    };

    // prologue: 4 chunks in flight
    issue_chunk(0);
    issue_chunk(1);
    issue_chunk(2);
    issue_chunk(3);

#pragma unroll 1
    for (int c = 0; c < NCHUNK; ++c) {
        cp_wait<3>();            // chunk c landed
        __syncthreads();         // all warps done reading stage (c-1)%5

        if (c + 4 < NCHUNK) issue_chunk(c + 4);   // refills stage (c-1)%5
        else cp_commit();        // keep group count consistent

        const uint32_t st = sb + (uint32_t)(c % STAGES) * STAGE_BYTES;

#pragma unroll
        for (int ks = 0; ks < 2; ++ks) {
            const int k0 = ks * 16;
            uint32_t af_hi[4], af_lo[4], bq_hi[2][4], bq_lo[2][4];
            {
                const int r = m_base + a_lrow;
                const int q = (k0 + a_koff) >> 3;
                const uint32_t ro = swz_off(r, q);
                ldsm_x4(af_hi, st + ST_AHI + ro);
                ldsm_x4(af_lo, st + ST_ALO + ro);
            }
#pragma unroll
            for (int p = 0; p < 2; ++p) {      // ni pairs (0,1) and (2,3)
                const int r = p * 16 + b_lrow;
                const int q = (k0 + b_koff) >> 3;
                const uint32_t ro = swz_off(r, q);
                ldsm_x4(bq_hi[p], st + ST_BHI + ro);
                ldsm_x4(bq_lo[p], st + ST_BLO + ro);
            }
#pragma unroll
            for (int ni = 0; ni < 4; ++ni) {
                const uint32_t* bh = &bq_hi[ni >> 1][(ni & 1) * 2];
                const uint32_t* bl = &bq_lo[ni >> 1][(ni & 1) * 2];
                mma_bf16(acc_hh[ni], af_hi, bh);  // hi*hi (own chain)
                mma_bf16(acc_x[ni],  af_hi, bl);  // hi*lo (cross chain)
                mma_bf16(acc_x[ni],  af_lo, bh);  // lo*hi
            }
        }
    }

    // ---- epilogue: gated sigmoid update, write fp32 state + bf16 split ----
    const float DEC = 0.6065306597126334f;  // exp(-0.5)
    const int tr = lane >> 2;
    const int tg = lane & 3;
#pragma unroll
    for (int half = 0; half < 2; ++half) {
        const int r = row0 + m_base + half * 8 + tr;
        const float tv = thr[r];
        const float ov = 1.0f - tv;
        const size_t base = (size_t)r * DD;
#pragma unroll
        for (int ni = 0; ni < 4; ++ni) {
            const int cn = col0 + ni * 8 + 2 * tg;
            const float2 hp = *(const float2*)(h_prev + base + cn);
            const float m0 = acc_hh[ni][half * 2 + 0] + acc_x[ni][half * 2 + 0];
            const float m1 = acc_hh[ni][half * 2 + 1] + acc_x[ni][half * 2 + 1];
            const float z0 = m0 * tv + hp.x * ov;
            const float z1 = m1 * tv + hp.y * ov;
            float2 res;
            res.x = DEC / (1.0f + __expf(-z0));
            res.y = DEC / (1.0f + __expf(-z1));
            *(float2*)(h_out + base + cn) = res;

            __nv_bfloat162 hh, ll;
            hh.x = __float2bfloat16(res.x);
            hh.y = __float2bfloat16(res.y);
            ll.x = __float2bfloat16(res.x - __bfloat162float(hh.x));
            ll.y = __float2bfloat16(res.y - __bfloat162float(hh.y));
            *(__nv_bfloat162*)(o_hi + base + cn) = hh;
            *(__nv_bfloat162*)(o_lo + base + cn) = ll;
        }
    }
}

// ---------------------------------------------------------------------------
// Prep: transpose + split W  ->  Wt[n][k] = W[k][n], bf16 hi/lo
// ---------------------------------------------------------------------------
__global__ void prep_w_kernel(const float* __restrict__ W,
                              __nv_bfloat16* __restrict__ wt_hi,
                              __nv_bfloat16* __restrict__ wt_lo)
{
    __shared__ float tile[32][33];
    const int n0 = blockIdx.x * 32;
    const int k0 = blockIdx.y * 32;
    const int tx = threadIdx.x;       // 0..31
    const int ty = threadIdx.y;       // 0..7
#pragma unroll
    for (int i = 0; i < 4; ++i)
        tile[ty + i * 8][tx] = W[(size_t)(k0 + ty + i * 8) * DD + n0 + tx];
    __syncthreads();
#pragma unroll
    for (int i = 0; i < 4; ++i) {
        const int a = ty + i * 8;
        const float v = tile[tx][a];
        const __nv_bfloat16 hb = __float2bfloat16(v);
        const size_t dst = (size_t)(n0 + a) * KDIM + k0 + tx;
        wt_hi[dst] = hb;
        wt_lo[dst] = __float2bfloat16(v - __bfloat162float(hb));
    }
}

// ---------------------------------------------------------------------------
// Split fp32 -> bf16 hi/lo (used for h0 and for ALL static data)
// ---------------------------------------------------------------------------
__global__ void split_kernel(const float* __restrict__ x,
                             __nv_bfloat16* __restrict__ hi,
                             __nv_bfloat16* __restrict__ lo,
                             long long n_elem)
{
    const long long i = ((long long)blockIdx.x * blockDim.x + threadIdx.x) * 4;
    if (i >= n_elem) return;
    const float4 v = *(const float4*)(x + i);
    __nv_bfloat162 h01, h23, l01, l23;
    h01.x = __float2bfloat16(v.x); h01.y = __float2bfloat16(v.y);
    h23.x = __float2bfloat16(v.z); h23.y = __float2bfloat16(v.w);
    l01.x = __float2bfloat16(v.x - __bfloat162float(h01.x));
    l01.y = __float2bfloat16(v.y - __bfloat162float(h01.y));
    l23.x = __float2bfloat16(v.z - __bfloat162float(h23.x));
    l23.y = __float2bfloat16(v.w - __bfloat162float(h23.y));
    *(__nv_bfloat162*)(hi + i)     = h01;
    *(__nv_bfloat162*)(hi + i + 2) = h23;
    *(__nv_bfloat162*)(lo + i)     = l01;
    *(__nv_bfloat162*)(lo + i + 2) = l23;
}

// ---------------------------------------------------------------------------
// out2[t] = states[t+1] - states[t]
// ---------------------------------------------------------------------------
__global__ void diff_kernel(const float* __restrict__ s0,
                            const float* __restrict__ out0,
                            float* __restrict__ out2)
{
    long long idx = ((long long)blockIdx.x * blockDim.x + threadIdx.x) * 4;
    const long long total = 63LL * ND;
    if (idx >= total) return;
    const int t = (int)(idx / ND);
    const long long r = idx - (long long)t * ND;
    const float* sp1 = out0 + (long long)(t + 1) * ND + r;
    const float* sp0 = (t == 0) ? (s0 + r) : (out0 + (long long)t * ND + r);
    float4 a = *(const float4*)sp1;
    float4 b = *(const float4*)sp0;
    float4 d;
    d.x = a.x - b.x; d.y = a.y - b.y; d.z = a.z - b.z; d.w = a.w - b.w;
    *(float4*)(out2 + idx) = d;
}

// ---------------------------------------------------------------------------
// Inputs: static [64,2048,512], thr [64,2048,1], h0 [2048,512], w1 [1024,512]
// Output: out0 [64,2048,512] | out1 [2048,512] | out2 [63,2048,512]
// ---------------------------------------------------------------------------
extern "C" void kernel_launch(void* const* d_in, const int* in_sizes, int n_in,
                              void* d_out, int out_size)
{
    const float* S   = (const float*)d_in[0];
    const float* thr = (const float*)d_in[1];
    const float* h0  = (const float*)d_in[2];
    const float* W   = (const float*)d_in[3];

    float* out0 = (float*)d_out;
    float* out1 = out0 + (long long)TT * ND;
    float* out2 = out1 + ND;

    float* s0 = nullptr;
    __nv_bfloat16 *hhi = nullptr, *hlo = nullptr, *wth = nullptr, *wtl = nullptr;
    __nv_bfloat16 *shi = nullptr, *slo = nullptr;
    cudaGetSymbolAddress((void**)&s0, g_state0);
    cudaGetSymbolAddress((void**)&hhi, g_h_hi);
    cudaGetSymbolAddress((void**)&hlo, g_h_lo);
    cudaGetSymbolAddress((void**)&wth, g_wt_hi);
    cudaGetSymbolAddress((void**)&wtl, g_wt_lo);
    cudaGetSymbolAddress((void**)&shi, g_s_hi);
    cudaGetSymbolAddress((void**)&slo, g_s_lo);
    __nv_bfloat16* hhi_b[2] = {hhi, hhi + ND};
    __nv_bfloat16* hlo_b[2] = {hlo, hlo + ND};

    cudaFuncSetAttribute(step_mma_kernel,
                         cudaFuncAttributeMaxDynamicSharedMemorySize, SMEM_TOTAL);

    // one-time prep (per launch)
    prep_w_kernel<<<dim3(16, 32), dim3(32, 8)>>>(W, wth, wtl);
    split_kernel<<<ND / 4 / 256, 256>>>(h0, hhi_b[0], hlo_b[0], (long long)ND);
    split_kernel<<<(unsigned)((long long)TT * ND / 4 / 256), 256>>>(
        S, shi, slo, (long long)TT * ND);

    const dim3 grid(DD / BN, NROWS / BM);  // (16, 16) = 256 CTAs

    // t = 0: carry-only state -> scratch; reads split buf0, writes buf1
    step_mma_kernel<<<grid, 256, SMEM_TOTAL>>>(
        hhi_b[0], hlo_b[0], shi, slo, h0, thr, wth, wtl,
        s0, hhi_b[1], hlo_b[1]);
    cudaMemcpyAsync(out0, h0, (size_t)ND * sizeof(float), cudaMemcpyDeviceToDevice);

    for (int t = 1; t < TT; ++t) {
        const int in = t & 1;
        const float* hp = (t == 1) ? (const float*)s0
                                   : (out0 + (long long)(t - 1) * ND);
        step_mma_kernel<<<grid, 256, SMEM_TOTAL>>>(
            hhi_b[in], hlo_b[in],
            shi + (long long)t * ND, slo + (long long)t * ND,
            hp, thr + (long long)t * NROWS,
            wth, wtl,
            out0 + (long long)t * ND,
            hhi_b[in ^ 1], hlo_b[in ^ 1]);
    }

    cudaMemcpyAsync(out1, out0 + 63LL * ND, (size_t)ND * sizeof(float),
                    cudaMemcpyDeviceToDevice);

    const long long total4 = (63LL * ND) / 4;
    const int threads = 256;
    const unsigned blocks = (unsigned)((total4 + threads - 1) / threads);
    diff_kernel<<<blocks, threads>>>(s0, out0, out2);
}

// round 14
// speedup vs baseline: 1.5440x; 1.1939x over previous
#include <cuda_runtime.h>
#include <cuda_bf16.h>
#include <cstdint>

// Problem constants
#define TT 64
#define NROWS 2048
#define DD 512
#define KDIM (2*DD)            // 1024
#define ND (NROWS * DD)        // 1,048,576

// ---------------------------------------------------------------------------
// Device scratch (no allocations allowed)
// ---------------------------------------------------------------------------
__device__ float g_state0[ND];                       // states[0] fp32 (carry only)
__device__ __nv_bfloat16 g_h_hi[2][ND];              // ping-pong bf16 split of h
__device__ __nv_bfloat16 g_h_lo[2][ND];
__device__ __nv_bfloat16 g_wt_hi[DD * KDIM];         // W^T split: [512 n][1024 k]
__device__ __nv_bfloat16 g_wt_lo[DD * KDIM];
__device__ __nv_bfloat16 g_s_hi[TT * ND];            // pre-split static (hi)
__device__ __nv_bfloat16 g_s_lo[TT * ND];            // pre-split static (lo)

// ---------------------------------------------------------------------------
// Warp-level primitives (sm_80+ PTX, safe for compute_103)
// ---------------------------------------------------------------------------
__device__ __forceinline__ uint32_t smem_u32(const void* p) {
    uint32_t a;
    asm("{ .reg .u64 t; cvta.to.shared.u64 t, %1; cvt.u32.u64 %0, t; }"
        : "=r"(a) : "l"(p));
    return a;
}

__device__ __forceinline__ void ldsm_x4(uint32_t* r, uint32_t addr) {
    asm volatile("ldmatrix.sync.aligned.m8n8.x4.shared.b16 {%0,%1,%2,%3}, [%4];"
                 : "=r"(r[0]), "=r"(r[1]), "=r"(r[2]), "=r"(r[3]) : "r"(addr));
}

__device__ __forceinline__ void mma_bf16(float* d, const uint32_t* a,
                                         const uint32_t* b) {
    asm volatile(
        "mma.sync.aligned.m16n8k16.row.col.f32.bf16.bf16.f32 "
        "{%0,%1,%2,%3}, {%4,%5,%6,%7}, {%8,%9}, {%0,%1,%2,%3};"
        : "+f"(d[0]), "+f"(d[1]), "+f"(d[2]), "+f"(d[3])
        : "r"(a[0]), "r"(a[1]), "r"(a[2]), "r"(a[3]), "r"(b[0]), "r"(b[1]));
}

__device__ __forceinline__ void cp16(uint32_t dst, const void* src) {
    asm volatile("cp.async.cg.shared.global [%0], [%1], 16;"
                 :: "r"(dst), "l"(src));
}
__device__ __forceinline__ void cp_commit() {
    asm volatile("cp.async.commit_group;");
}
template <int N>
__device__ __forceinline__ void cp_wait() {
    asm volatile("cp.async.wait_group %0;" :: "n"(N));
}

// XOR swizzle for 64B rows (4x16B quads): conflict-free for 8-row ldmatrix
// phases and warp STS. phys_quad = q ^ ((r>>1)&3).
__device__ __forceinline__ uint32_t swz_off(int r, int q) {
    return (uint32_t)((r << 6) + ((q ^ ((r >> 1) & 3)) << 4));
}

// ---------------------------------------------------------------------------
// Step kernel:
//   MM = h_prev @ W[0:512] + static_t @ W[512:1024]   (split-bf16, fp32 acc)
//   h  = sigmoid(MM*thr + h_prev*(1-thr)) * exp(-1/2)
// CTA tile 64x64, 4 warps (2M x 2N), warp tile 32x32, BK=32.
// 5-stage cp.async pipeline (4-deep prefetch); 2 CTAs/SM where grid allows.
// ---------------------------------------------------------------------------
#define BM 64
#define BN 64
#define BK 32
#define NCHUNK (KDIM / BK)     // 32
#define STAGES 5

// per-stage byte offsets; rows are exactly 64B (32 bf16), XOR-swizzled
#define ST_AHI 0
#define ST_ALO 4096            // 64*64
#define ST_BHI 8192
#define ST_BLO 12288
#define STAGE_BYTES 16384
#define SMEM_TOTAL (STAGES * STAGE_BYTES)   // 81920 per CTA (2/SM = 160KB)

__global__ void __launch_bounds__(128, 2) step_mma_kernel(
    const __nv_bfloat16* __restrict__ h_hi,   // [N, DD] phase-0 A (hi)
    const __nv_bfloat16* __restrict__ h_lo,
    const __nv_bfloat16* __restrict__ s_hi,   // [N, DD] phase-1 A (hi), this step
    const __nv_bfloat16* __restrict__ s_lo,
    const float* __restrict__ h_prev,         // [N, DD] fp32 (gate input)
    const float* __restrict__ thr,            // [N]
    const __nv_bfloat16* __restrict__ wt_hi,  // [DD, KDIM] W^T hi
    const __nv_bfloat16* __restrict__ wt_lo,
    float* __restrict__ h_out,                // [N, DD] fp32
    __nv_bfloat16* __restrict__ o_hi,         // split of new h
    __nv_bfloat16* __restrict__ o_lo)
{
    extern __shared__ char smem[];
    const uint32_t sb = smem_u32(smem);

    const int tid  = threadIdx.x;
    const int lane = tid & 31;
    const int warp = tid >> 5;           // 0..3 (2M x 2N)
    const int m_base = (warp >> 1) * 32;
    const int n_base = (warp & 1) * 32;
    const int row0 = blockIdx.y * BM;
    const int col0 = blockIdx.x * BN;

    // ldmatrix lane maps
    // A (16x16, x4): lanes 0-15 -> rows m..m+15 @ k0; lanes 16-31 -> @ k0+8
    const int a_lrow = (lane & 7) + ((lane >> 3) & 1) * 8;
    const int a_koff = ((lane >> 4) & 1) * 8;
    // B paired x4: 8-lane groups -> (n0,k0),(n0,k0+8),(n0+8,k0),(n0+8,k0+8)
    const int b_lrow = ((lane >> 4) & 1) * 8 + (lane & 7);
    const int b_koff = ((lane >> 3) & 1) * 8;

    float acc_hh[2][4][4];               // [mi][ni] hi*hi accumulators
    float acc_x[2][4][4];                // [mi][ni] hi*lo + lo*hi accumulators
#pragma unroll
    for (int mi = 0; mi < 2; ++mi)
#pragma unroll
        for (int ni = 0; ni < 4; ++ni)
#pragma unroll
            for (int j = 0; j < 4; ++j) {
                acc_hh[mi][ni][j] = 0.0f;
                acc_x[mi][ni][j] = 0.0f;
            }

    // ---- async tile fill for chunk c into stage (c % STAGES) ----
    // A: 64 rows x 32 k (hi+lo): 256 cp16 per tile -> 2/thread each
    // B: 64 rows x 32 k (hi+lo): 256 cp16 per tile -> 2/thread each
    auto issue_chunk = [&](int c) {
        const uint32_t st = sb + (uint32_t)(c % STAGES) * STAGE_BYTES;
        const int ph  = c >> 4;
        const int kkA = (c & 15) * BK;
        const int kkW = c * BK;
        const __nv_bfloat16* ah = ph ? s_hi : h_hi;
        const __nv_bfloat16* al = ph ? s_lo : h_lo;
#pragma unroll
        for (int i = 0; i < 2; ++i) {
            const int o = tid + i * 128;       // 0..255
            const int r = o >> 2;              // 0..63
            const int q = o & 3;
            const size_t srcA = (size_t)(row0 + r) * DD + kkA + q * 8;
            const size_t srcB = (size_t)(col0 + r) * KDIM + kkW + q * 8;
            const uint32_t dst = st + swz_off(r, q);
            cp16(dst + ST_AHI, ah + srcA);
            cp16(dst + ST_ALO, al + srcA);
            cp16(dst + ST_BHI, wt_hi + srcB);
            cp16(dst + ST_BLO, wt_lo + srcB);
        }
        cp_commit();
    };

    // prologue: 4 chunks in flight
    issue_chunk(0);
    issue_chunk(1);
    issue_chunk(2);
    issue_chunk(3);

#pragma unroll 1
    for (int c = 0; c < NCHUNK; ++c) {
        cp_wait<3>();            // chunk c landed
        __syncthreads();         // all warps done reading stage (c-1)%5

        if (c + 4 < NCHUNK) issue_chunk(c + 4);   // refills stage (c-1)%5
        else cp_commit();        // keep group count consistent

        const uint32_t st = sb + (uint32_t)(c % STAGES) * STAGE_BYTES;

#pragma unroll
        for (int ks = 0; ks < 2; ++ks) {
            const int k0 = ks * 16;
            const int q = (k0 >> 3);     // base quad for this ks (koff adds)
            uint32_t af_hi[2][4], af_lo[2][4], bq_hi[2][4], bq_lo[2][4];
#pragma unroll
            for (int mi = 0; mi < 2; ++mi) {
                const int r = m_base + mi * 16 + a_lrow;
                const uint32_t ro = swz_off(r, (k0 + a_koff) >> 3);
                ldsm_x4(af_hi[mi], st + ST_AHI + ro);
                ldsm_x4(af_lo[mi], st + ST_ALO + ro);
            }
#pragma unroll
            for (int p = 0; p < 2; ++p) {      // ni pairs (0,1) and (2,3)
                const int r = n_base + p * 16 + b_lrow;
                const uint32_t ro = swz_off(r, (k0 + b_koff) >> 3);
                ldsm_x4(bq_hi[p], st + ST_BHI + ro);
                ldsm_x4(bq_lo[p], st + ST_BLO + ro);
            }
            (void)q;
#pragma unroll
            for (int mi = 0; mi < 2; ++mi)
#pragma unroll
                for (int ni = 0; ni < 4; ++ni) {
                    const uint32_t* bh = &bq_hi[ni >> 1][(ni & 1) * 2];
                    const uint32_t* bl = &bq_lo[ni >> 1][(ni & 1) * 2];
                    mma_bf16(acc_hh[mi][ni], af_hi[mi], bh);  // hi*hi
                    mma_bf16(acc_x[mi][ni],  af_hi[mi], bl);  // hi*lo
                    mma_bf16(acc_x[mi][ni],  af_lo[mi], bh);  // lo*hi
                }
        }
    }

    // ---- epilogue: gated sigmoid update, write fp32 state + bf16 split ----
    const float DEC = 0.6065306597126334f;  // exp(-0.5)
    const int tr = lane >> 2;
    const int tg = lane & 3;
#pragma unroll
    for (int mi = 0; mi < 2; ++mi) {
#pragma unroll
        for (int half = 0; half < 2; ++half) {
            const int r = row0 + m_base + mi * 16 + half * 8 + tr;
            const float tv = thr[r];
            const float ov = 1.0f - tv;
            const size_t base = (size_t)r * DD;
#pragma unroll
            for (int ni = 0; ni < 4; ++ni) {
                const int cn = col0 + n_base + ni * 8 + 2 * tg;
                const float2 hp = *(const float2*)(h_prev + base + cn);
                const float m0 = acc_hh[mi][ni][half * 2 + 0] + acc_x[mi][ni][half * 2 + 0];
                const float m1 = acc_hh[mi][ni][half * 2 + 1] + acc_x[mi][ni][half * 2 + 1];
                const float z0 = m0 * tv + hp.x * ov;
                const float z1 = m1 * tv + hp.y * ov;
                float2 res;
                res.x = DEC / (1.0f + __expf(-z0));
                res.y = DEC / (1.0f + __expf(-z1));
                *(float2*)(h_out + base + cn) = res;

                __nv_bfloat162 hh, ll;
                hh.x = __float2bfloat16(res.x);
                hh.y = __float2bfloat16(res.y);
                ll.x = __float2bfloat16(res.x - __bfloat162float(hh.x));
                ll.y = __float2bfloat16(res.y - __bfloat162float(hh.y));
                *(__nv_bfloat162*)(o_hi + base + cn) = hh;
                *(__nv_bfloat162*)(o_lo + base + cn) = ll;
            }
        }
    }
}

// ---------------------------------------------------------------------------
// Prep: transpose + split W  ->  Wt[n][k] = W[k][n], bf16 hi/lo
// ---------------------------------------------------------------------------
__global__ void prep_w_kernel(const float* __restrict__ W,
                              __nv_bfloat16* __restrict__ wt_hi,
                              __nv_bfloat16* __restrict__ wt_lo)
{
    __shared__ float tile[32][33];
    const int n0 = blockIdx.x * 32;
    const int k0 = blockIdx.y * 32;
    const int tx = threadIdx.x;       // 0..31
    const int ty = threadIdx.y;       // 0..7
#pragma unroll
    for (int i = 0; i < 4; ++i)
        tile[ty + i * 8][tx] = W[(size_t)(k0 + ty + i * 8) * DD + n0 + tx];
    __syncthreads();
#pragma unroll
    for (int i = 0; i < 4; ++i) {
        const int a = ty + i * 8;
        const float v = tile[tx][a];
        const __nv_bfloat16 hb = __float2bfloat16(v);
        const size_t dst = (size_t)(n0 + a) * KDIM + k0 + tx;
        wt_hi[dst] = hb;
        wt_lo[dst] = __float2bfloat16(v - __bfloat162float(hb));
    }
}

// ---------------------------------------------------------------------------
// Split fp32 -> bf16 hi/lo (used for h0 and for ALL static data)
// ---------------------------------------------------------------------------
__global__ void split_kernel(const float* __restrict__ x,
                             __nv_bfloat16* __restrict__ hi,
                             __nv_bfloat16* __restrict__ lo,
                             long long n_elem)
{
    const long long i = ((long long)blockIdx.x * blockDim.x + threadIdx.x) * 4;
    if (i >= n_elem) return;
    const float4 v = *(const float4*)(x + i);
    __nv_bfloat162 h01, h23, l01, l23;
    h01.x = __float2bfloat16(v.x); h01.y = __float2bfloat16(v.y);
    h23.x = __float2bfloat16(v.z); h23.y = __float2bfloat16(v.w);
    l01.x = __float2bfloat16(v.x - __bfloat162float(h01.x));
    l01.y = __float2bfloat16(v.y - __bfloat162float(h01.y));
    l23.x = __float2bfloat16(v.z - __bfloat162float(h23.x));
    l23.y = __float2bfloat16(v.w - __bfloat162float(h23.y));
    *(__nv_bfloat162*)(hi + i)     = h01;
    *(__nv_bfloat162*)(hi + i + 2) = h23;
    *(__nv_bfloat162*)(lo + i)     = l01;
    *(__nv_bfloat162*)(lo + i + 2) = l23;
}

// ---------------------------------------------------------------------------
// out2[t] = states[t+1] - states[t]
// ---------------------------------------------------------------------------
__global__ void diff_kernel(const float* __restrict__ s0,
                            const float* __restrict__ out0,
                            float* __restrict__ out2)
{
    long long idx = ((long long)blockIdx.x * blockDim.x + threadIdx.x) * 4;
    const long long total = 63LL * ND;
    if (idx >= total) return;
    const int t = (int)(idx / ND);
    const long long r = idx - (long long)t * ND;
    const float* sp1 = out0 + (long long)(t + 1) * ND + r;
    const float* sp0 = (t == 0) ? (s0 + r) : (out0 + (long long)t * ND + r);
    float4 a = *(const float4*)sp1;
    float4 b = *(const float4*)sp0;
    float4 d;
    d.x = a.x - b.x; d.y = a.y - b.y; d.z = a.z - b.z; d.w = a.w - b.w;
    *(float4*)(out2 + idx) = d;
}

// ---------------------------------------------------------------------------
// Inputs: static [64,2048,512], thr [64,2048,1], h0 [2048,512], w1 [1024,512]
// Output: out0 [64,2048,512] | out1 [2048,512] | out2 [63,2048,512]
// ---------------------------------------------------------------------------
extern "C" void kernel_launch(void* const* d_in, const int* in_sizes, int n_in,
                              void* d_out, int out_size)
{
    const float* S   = (const float*)d_in[0];
    const float* thr = (const float*)d_in[1];
    const float* h0  = (const float*)d_in[2];
    const float* W   = (const float*)d_in[3];

    float* out0 = (float*)d_out;
    float* out1 = out0 + (long long)TT * ND;
    float* out2 = out1 + ND;

    float* s0 = nullptr;
    __nv_bfloat16 *hhi = nullptr, *hlo = nullptr, *wth = nullptr, *wtl = nullptr;
    __nv_bfloat16 *shi = nullptr, *slo = nullptr;
    cudaGetSymbolAddress((void**)&s0, g_state0);
    cudaGetSymbolAddress((void**)&hhi, g_h_hi);
    cudaGetSymbolAddress((void**)&hlo, g_h_lo);
    cudaGetSymbolAddress((void**)&wth, g_wt_hi);
    cudaGetSymbolAddress((void**)&wtl, g_wt_lo);
    cudaGetSymbolAddress((void**)&shi, g_s_hi);
    cudaGetSymbolAddress((void**)&slo, g_s_lo);
    __nv_bfloat16* hhi_b[2] = {hhi, hhi + ND};
    __nv_bfloat16* hlo_b[2] = {hlo, hlo + ND};

    cudaFuncSetAttribute(step_mma_kernel,
                         cudaFuncAttributeMaxDynamicSharedMemorySize, SMEM_TOTAL);

    // one-time prep (per launch)
    prep_w_kernel<<<dim3(16, 32), dim3(32, 8)>>>(W, wth, wtl);
    split_kernel<<<ND / 4 / 256, 256>>>(h0, hhi_b[0], hlo_b[0], (long long)ND);
    split_kernel<<<(unsigned)((long long)TT * ND / 4 / 256), 256>>>(
        S, shi, slo, (long long)TT * ND);

    const dim3 grid(DD / BN, NROWS / BM);  // (8, 32) = 256 CTAs

    // t = 0: carry-only state -> scratch; reads split buf0, writes buf1
    step_mma_kernel<<<grid, 128, SMEM_TOTAL>>>(
        hhi_b[0], hlo_b[0], shi, slo, h0, thr, wth, wtl,
        s0, hhi_b[1], hlo_b[1]);
    cudaMemcpyAsync(out0, h0, (size_t)ND * sizeof(float), cudaMemcpyDeviceToDevice);

    for (int t = 1; t < TT; ++t) {
        const int in = t & 1;
        const float* hp = (t == 1) ? (const float*)s0
                                   : (out0 + (long long)(t - 1) * ND);
        step_mma_kernel<<<grid, 128, SMEM_TOTAL>>>(
            hhi_b[in], hlo_b[in],
            shi + (long long)t * ND, slo + (long long)t * ND,
            hp, thr + (long long)t * NROWS,
            wth, wtl,
            out0 + (long long)t * ND,
            hhi_b[in ^ 1], hlo_b[in ^ 1]);
    }

    cudaMemcpyAsync(out1, out0 + 63LL * ND, (size_t)ND * sizeof(float),
                    cudaMemcpyDeviceToDevice);

    const long long total4 = (63LL * ND) / 4;
    const int threads = 256;
    const unsigned blocks = (unsigned)((total4 + threads - 1) / threads);
    diff_kernel<<<blocks, threads>>>(s0, out0, out2);
}